// round 14
// baseline (speedup 1.0000x reference)
#include <cuda_runtime.h>
#include <cuda_fp16.h>
#include <math.h>
#include <stdint.h>

constexpr int CB   = 2;
constexpr int CL   = 1024;
constexpr int CD   = 1024;
constexpr int CDIN = 2048;
constexpr int CN   = 16;
constexpr int CR   = 64;
constexpr int CK   = 4;
constexpr int CML  = CB * CL;      // 2048
constexpr int CXD  = CR + 2 * CN;  // 96
constexpr int KSPL = 8;
constexpr float CLN_EPS = 1e-5f;

// ---------------- scratch ----------------
__device__ float g_xz    [CML * (2*CDIN)];
__device__ float g_xcT   [CDIN * CML];        // conv output, [d][t]
__device__ float g_xdblT [CXD * CML];         // x_dbl transposed [c][t]
__device__ float g_delta [CML * CDIN];        // [t][d]
__device__ float g_pre   [CML * CD];
__device__ float g_part  [KSPL * CML * CXD];
__device__ float g_part4 [2 * CML * CD];      // G4 split-K partials

__device__ uint32_t g_xp    [CML * (CD/2)];
__device__ uint32_t g_Winp_h[(2*CDIN) * (CD/2)],  g_Winp_l[(2*CDIN) * (CD/2)];
__device__ uint32_t g_Wxp_h [CXD * (CDIN/2)],     g_Wxp_l [CXD * (CDIN/2)];
__device__ uint32_t g_Wdtp_h[CDIN * (CR/2)],      g_Wdtp_l[CDIN * (CR/2)];
__device__ uint32_t g_Woutp_h[CD * (CDIN/2)],     g_Woutp_l[CD * (CDIN/2)];
__device__ uint16_t g_xcp [CML * CDIN];
__device__ uint16_t g_xdp [CML * CXD];
__device__ uint16_t g_ygp [CML * CDIN];

// ---------------- helpers ----------------
__device__ __forceinline__ uint16_t to_fp16(float x)
{
    return __half_as_ushort(__float2half_rn(x));
}

__device__ __forceinline__ void split_fp16(float x, uint16_t& h, uint16_t& l)
{
    __half hh = __float2half_rn(x);
    float r = x - __half2float(hh);
    __half ll = __float2half_rn(r);
    h = __half_as_ushort(hh);
    l = __half_as_ushort(ll);
}

__device__ __forceinline__ void mma_fp16(float* acc, const uint32_t* a, const uint32_t* b)
{
    asm volatile(
        "mma.sync.aligned.m16n8k16.row.col.f32.f16.f16.f32 "
        "{%0,%1,%2,%3}, {%4,%5,%6,%7}, {%8,%9}, {%0,%1,%2,%3};\n"
        : "+f"(acc[0]), "+f"(acc[1]), "+f"(acc[2]), "+f"(acc[3])
        : "r"(a[0]), "r"(a[1]), "r"(a[2]), "r"(a[3]), "r"(b[0]), "r"(b[1]));
}

__device__ __forceinline__ void cp_async16(uint32_t smem_addr, const void* gptr)
{
    asm volatile("cp.async.cg.shared.global [%0], [%1], 16;\n" :: "r"(smem_addr), "l"(gptr));
}

__device__ __forceinline__ uint32_t smem_u32(const void* p)
{
    uint32_t a;
    asm("{ .reg .u64 t; cvta.to.shared.u64 t, %1; cvt.u32.u64 %0, t; }" : "=r"(a) : "l"(p));
    return a;
}

// ---------------- pack x ----------------
__global__ void pack_x_kernel(const float* __restrict__ x)
{
    int i = blockIdx.x * blockDim.x + threadIdx.x;
    if (i >= CML * (CD/2)) return;
    uint16_t h0 = to_fp16(x[2*i]);
    uint16_t h1 = to_fp16(x[2*i + 1]);
    g_xp[i] = (uint32_t)h0 | ((uint32_t)h1 << 16);
}

// ---------------- transpose-pack weight body ----------------
__device__ __forceinline__ void pack_w_body(const float* __restrict__ W, int K, int N,
                                            uint32_t* __restrict__ oh, uint32_t* __restrict__ ol,
                                            int k0, int n0, float (*sm)[33])
{
    int t = threadIdx.x;
    int c = t & 31;
    int r0 = t >> 5;
    #pragma unroll
    for (int it = 0; it < 8; it++) {
        int r = r0 + it * 8;
        sm[r][c] = W[(size_t)(k0 + r) * N + n0 + c];
    }
    __syncthreads();
    int k2 = t & 31;
    int nn0 = t >> 5;
    #pragma unroll
    for (int it = 0; it < 4; it++) {
        int n = nn0 + it * 8;
        float v0 = sm[2*k2    ][n];
        float v1 = sm[2*k2 + 1][n];
        uint16_t h0, l0, h1, l1;
        split_fp16(v0, h0, l0);
        split_fp16(v1, h1, l1);
        size_t o = (size_t)(n0 + n) * (K/2) + k0/2 + k2;
        oh[o] = (uint32_t)h0 | ((uint32_t)h1 << 16);
        ol[o] = (uint32_t)l0 | ((uint32_t)l1 << 16);
    }
}

__global__ void pack_w_kernel(const float* __restrict__ W, int K, int N,
                              uint32_t* __restrict__ oh, uint32_t* __restrict__ ol)
{
    __shared__ float sm[64][33];
    pack_w_body(W, K, N, oh, ol, blockIdx.x * 64, blockIdx.y * 32, sm);
}

__global__ void pack_w3_kernel(const float* __restrict__ Wx,
                               const float* __restrict__ Wdt,
                               const float* __restrict__ Wout,
                               uint32_t* __restrict__ oxh, uint32_t* __restrict__ oxl,
                               uint32_t* __restrict__ odh, uint32_t* __restrict__ odl,
                               uint32_t* __restrict__ ooh, uint32_t* __restrict__ ool)
{
    __shared__ float sm[64][33];
    int gy = blockIdx.y;
    const float* W; int K, N; uint32_t *oh, *ol; int ny;
    if (gy < 3)       { W = Wx;   K = CDIN; N = CXD;  oh = oxh; ol = oxl; ny = gy; }
    else if (gy < 67) { W = Wdt;  K = CR;   N = CDIN; oh = odh; ol = odl; ny = gy - 3; }
    else              { W = Wout; K = CDIN; N = CD;   oh = ooh; ol = ool; ny = gy - 67; }
    int k0 = blockIdx.x * 64;
    if (k0 >= K) return;
    pack_w_body(W, K, N, oh, ol, k0, ny * 32, sm);
}

// ---------------- fp16 tensor-core GEMM ----------------
constexpr int BM = 128, BN = 128;
constexpr int STR = 20;
constexpr int PLANE = 128 * STR;
constexpr int STAGE_U = 3 * PLANE;
constexpr int GEMM_SMEM = 2 * STAGE_U * 4;

template<int EPI>
__global__ __launch_bounds__(256, 2)
void tgemm5(int M, int N,
            const uint32_t* __restrict__ A_g, int lda2,
            const uint32_t* __restrict__ Bh_g, const uint32_t* __restrict__ Bl_g, int ldb2,
            float* __restrict__ C, int ldc, const float* __restrict__ bias,
            int k2_begin, int ntiles, int zstride)
{
    extern __shared__ uint32_t sm[];

    const int tid  = threadIdx.x;
    const int warp = tid >> 5;
    const int lane = tid & 31;
    const int g    = lane >> 2;
    const int tg   = lane & 3;

    const int row0 = blockIdx.y * BM;
    const int col0 = blockIdx.x * BN;
    const int wm0  = (warp >> 2) * 64;
    const int wn0  = (warp & 3) * 32;

    const int k2b = k2_begin + blockIdx.z * zstride;

    float acc[4][4][4];
    #pragma unroll
    for (int i = 0; i < 4; i++)
        #pragma unroll
        for (int j = 0; j < 4; j++)
            #pragma unroll
            for (int r = 0; r < 4; r++) acc[i][j][r] = 0.f;

    if (N < BN) {
        int nz = BN - N;
        int total = 2 * 2 * nz * 16;
        for (int idx = tid; idx < total; idx += 256) {
            int lin = idx;
            int w  = lin & 15; lin >>= 4;
            int rq = lin % nz; lin /= nz;
            int pl = lin & 1;  lin >>= 1;
            int sq = lin;
            sm[sq * STAGE_U + (1 + pl) * PLANE + (N + rq) * STR + w] = 0;
        }
    }
    __syncthreads();

    auto load_stage = [&](int stg, int kt) {
        uint32_t* base = sm + stg * STAGE_U;
        const int kcol = k2b + kt * 16;
        #pragma unroll
        for (int i = 0; i < 2; i++) {
            int u = tid + 256 * i;
            int r = u >> 2, c4 = (u & 3) * 4;
            cp_async16(smem_u32(&base[r * STR + c4]),
                       A_g + (size_t)(row0 + r) * lda2 + kcol + c4);
        }
        #pragma unroll
        for (int i = 0; i < 4; i++) {
            int u = tid + 256 * i;
            int pl = u >> 9;
            int v = u & 511;
            int r = v >> 2, c4 = (v & 3) * 4;
            if (col0 + r < N) {
                const uint32_t* src = pl ? Bl_g : Bh_g;
                cp_async16(smem_u32(&base[(1 + pl) * PLANE + r * STR + c4]),
                           src + (size_t)(col0 + r) * ldb2 + kcol + c4);
            }
        }
    };

    load_stage(0, 0);
    asm volatile("cp.async.commit_group;\n" ::: "memory");

    int stg = 0;
    for (int kt = 0; kt < ntiles; kt++) {
        if (kt + 1 < ntiles) {
            load_stage(stg ^ 1, kt + 1);
            asm volatile("cp.async.commit_group;\n" ::: "memory");
            asm volatile("cp.async.wait_group 1;\n" ::: "memory");
        } else {
            asm volatile("cp.async.wait_group 0;\n" ::: "memory");
        }
        __syncthreads();

        const uint32_t* Ap = sm + stg * STAGE_U;
        const uint32_t* Bh = Ap + PLANE;
        const uint32_t* Bl = Ap + 2 * PLANE;

        #pragma unroll
        for (int ks = 0; ks < 2; ks++) {
            const int ko = ks * 8;
            uint32_t af[4][4];
            #pragma unroll
            for (int mt = 0; mt < 4; mt++) {
                int r = wm0 + mt * 16 + g;
                af[mt][0] = Ap[ r      * STR + ko + tg    ];
                af[mt][1] = Ap[(r + 8) * STR + ko + tg    ];
                af[mt][2] = Ap[ r      * STR + ko + tg + 4];
                af[mt][3] = Ap[(r + 8) * STR + ko + tg + 4];
            }
            uint32_t bfh[4][2], bfl[4][2];
            #pragma unroll
            for (int nt = 0; nt < 4; nt++) {
                int c = wn0 + nt * 8 + g;
                bfh[nt][0] = Bh[c * STR + ko + tg    ];
                bfh[nt][1] = Bh[c * STR + ko + tg + 4];
                bfl[nt][0] = Bl[c * STR + ko + tg    ];
                bfl[nt][1] = Bl[c * STR + ko + tg + 4];
            }
            #pragma unroll
            for (int mt = 0; mt < 4; mt++)
                #pragma unroll
                for (int nt = 0; nt < 4; nt++) {
                    mma_fp16(acc[mt][nt], af[mt], bfh[nt]);
                    mma_fp16(acc[mt][nt], af[mt], bfl[nt]);
                }
        }
        __syncthreads();
        stg ^= 1;
    }

    float* Cz = C + (size_t)blockIdx.z * CML * ldc;

    #pragma unroll
    for (int mt = 0; mt < 4; mt++) {
        int r0 = row0 + wm0 + mt * 16 + g;
        #pragma unroll
        for (int nt = 0; nt < 4; nt++) {
            int c0 = col0 + wn0 + nt * 8 + 2 * tg;
            #pragma unroll
            for (int rr = 0; rr < 2; rr++) {
                int r = r0 + rr * 8;
                #pragma unroll
                for (int cc = 0; cc < 2; cc++) {
                    int c = c0 + cc;
                    if (c < N) {
                        float v = acc[mt][nt][rr * 2 + cc];
                        if (EPI == 1) {
                            v = v + bias[c];
                            v = (v > 20.f) ? v : log1pf(__expf(v));
                        }
                        Cz[(size_t)r * ldc + c] = v;
                    }
                }
            }
        }
    }
}

// ---------------- split-K reduce for G2: writes xdblT fp32 + xdp fp16 ----------------
__global__ void reduce_xdbl_kernel(const float* __restrict__ part,
                                   float* __restrict__ xdblT,
                                   uint16_t* __restrict__ xdp)
{
    int i = blockIdx.x * blockDim.x + threadIdx.x;
    if (i >= CML * CXD) return;
    float s = 0.f;
    #pragma unroll
    for (int z = 0; z < KSPL; z++) s += part[(size_t)z * CML * CXD + i];
    int r = i / CXD;     // t
    int c = i % CXD;
    xdblT[(size_t)c * CML + r] = s;
    xdp[i] = to_fp16(s);
}

// ---------------- tiled conv + SiLU: writes xcp [t][d] + xcT [d][t] ----------------
// grid: (CML/64, CDIN/32), block 256
__global__ __launch_bounds__(256)
void conv_silu_kernel(const float* __restrict__ xz,
                      const float* __restrict__ conv_w,
                      const float* __restrict__ conv_b,
                      uint16_t* __restrict__ xcp,
                      float* __restrict__ xcT)
{
    __shared__ float si[67][33];
    __shared__ float so[32][65];

    const int bl0 = blockIdx.x * 64;        // time-tile start (never crosses batch: 64 | 1024)
    const int d0  = blockIdx.y * 32;
    const int l0  = bl0 & (CL - 1);
    const int b   = bl0 >> 10;
    const int tid = threadIdx.x;
    const int dx  = tid & 31;
    const int ty  = tid >> 5;

    // load input rows l0-3 .. l0+63 for 32 channels
    for (int j = ty; j < 67; j += 8) {
        int l = l0 - 3 + j;
        float v = 0.f;
        if (l >= 0)
            v = xz[(size_t)(b * CL + l) * (2 * CDIN) + d0 + dx];
        si[j][dx] = v;
    }
    __syncthreads();

    const int d = d0 + dx;
    float w0 = conv_w[d * CK + 0];
    float w1 = conv_w[d * CK + 1];
    float w2 = conv_w[d * CK + 2];
    float w3 = conv_w[d * CK + 3];
    float bb = conv_b[d];

    for (int j = ty; j < 64; j += 8) {
        float acc = bb;
        acc = fmaf(si[j    ][dx], w0, acc);
        acc = fmaf(si[j + 1][dx], w1, acc);
        acc = fmaf(si[j + 2][dx], w2, acc);
        acc = fmaf(si[j + 3][dx], w3, acc);
        float sig = 1.f / (1.f + __expf(-acc));
        float v = acc * sig;
        xcp[(size_t)(bl0 + j) * CDIN + d] = to_fp16(v);
        so[dx][j] = v;
    }
    __syncthreads();

    // write xcT coalesced along t
    #pragma unroll
    for (int it = 0; it < 2; it++) {
        int u = tid + 256 * it;       // 0..511
        int row = u >> 4;             // 0..31
        int qf  = u & 15;             // float4 index
        float4 v = make_float4(so[row][qf*4], so[row][qf*4+1],
                               so[row][qf*4+2], so[row][qf*4+3]);
        *reinterpret_cast<float4*>(xcT + (size_t)(d0 + row) * CML + bl0 + qf * 4) = v;
    }
}

// ---------------- selective scan: float4 loads + fused gate/pack ----------------
__global__ __launch_bounds__(128)
void scan_kernel(const float* __restrict__ delta,    // [t][d]
                 const float* __restrict__ xcT,      // [d][t]
                 const float* __restrict__ xdblT,    // [c][t]
                 const float* __restrict__ xz,       // for z
                 const float* __restrict__ A_log,
                 const float* __restrict__ D_skip,
                 uint16_t* __restrict__ ygp)
{
    int warp = (blockIdx.x * blockDim.x + threadIdx.x) >> 5;
    int lane = threadIdx.x & 31;
    int half = lane >> 4;
    int n    = lane & 15;

    int b = warp >> 10;
    int d = ((warp & 1023) << 1) + half;

    float a_coef = -expf(A_log[d * CN + n]);
    float d_skip = D_skip[d];
    float h = 0.f;

    const size_t bl0 = (size_t)b * CL;
    const float4* xT = reinterpret_cast<const float4*>(xcT   + (size_t)d * CML + bl0);
    const float4* BT = reinterpret_cast<const float4*>(xdblT + (size_t)(CR + n) * CML + bl0);
    const float4* CT = reinterpret_cast<const float4*>(xdblT + (size_t)(CR + CN + n) * CML + bl0);

    for (int q = 0; q < CL / 4; q++) {
        int t0 = q * 4;
        float dv[4];
        #pragma unroll
        for (int u = 0; u < 4; u++)
            dv[u] = delta[(bl0 + t0 + u) * CDIN + d];
        float4 xv4 = xT[q];
        float4 B4  = BT[q];
        float4 C4  = CT[q];
        float xv[4] = {xv4.x, xv4.y, xv4.z, xv4.w};
        float Bn[4] = {B4.x, B4.y, B4.z, B4.w};
        float Cn[4] = {C4.x, C4.y, C4.z, C4.w};

        #pragma unroll
        for (int u = 0; u < 4; u++) {
            float dA = __expf(dv[u] * a_coef);
            h = fmaf(dA, h, dv[u] * Bn[u] * xv[u]);

            float v = h * Cn[u];
            v += __shfl_xor_sync(0xffffffffu, v, 8);
            v += __shfl_xor_sync(0xffffffffu, v, 4);
            v += __shfl_xor_sync(0xffffffffu, v, 2);
            v += __shfl_xor_sync(0xffffffffu, v, 1);

            if (n == 0) {
                size_t bl = bl0 + t0 + u;
                float zv = xz[bl * (2 * CDIN) + CDIN + d];
                float yv = v + xv[u] * d_skip;
                float sig = 1.f / (1.f + __expf(-zv));
                ygp[bl * CDIN + d] = to_fp16(yv * (zv * sig));
            }
        }
    }
}

// ---------------- G4 split-K reduce ----------------
__global__ void reduce_pre_kernel(const float* __restrict__ part,
                                  float* __restrict__ pre)
{
    int i = blockIdx.x * blockDim.x + threadIdx.x;
    if (i >= CML * CD) return;
    pre[i] = part[i] + part[(size_t)CML * CD + i];
}

// ---------------- LayerNorm ----------------
__global__ __launch_bounds__(256)
void ln_kernel(const float* __restrict__ pre,
               const float* __restrict__ gamma,
               const float* __restrict__ beta,
               float* __restrict__ out)
{
    int row = blockIdx.x;
    const float* p = pre + (size_t)row * CD;
    int tid = threadIdx.x;

    float s = 0.f, s2 = 0.f;
    for (int c = tid; c < CD; c += 256) {
        float v = p[c];
        s  += v;
        s2 += v * v;
    }
    #pragma unroll
    for (int o = 16; o >= 1; o >>= 1) {
        s  += __shfl_xor_sync(0xffffffffu, s,  o);
        s2 += __shfl_xor_sync(0xffffffffu, s2, o);
    }
    __shared__ float shs[8], shs2[8];
    int wid = tid >> 5;
    if ((tid & 31) == 0) { shs[wid] = s; shs2[wid] = s2; }
    __syncthreads();
    if (tid < 32) {
        s  = (tid < 8) ? shs[tid]  : 0.f;
        s2 = (tid < 8) ? shs2[tid] : 0.f;
        #pragma unroll
        for (int o = 4; o >= 1; o >>= 1) {
            s  += __shfl_xor_sync(0xffffffffu, s,  o);
            s2 += __shfl_xor_sync(0xffffffffu, s2, o);
        }
        if (tid == 0) { shs[0] = s; shs2[0] = s2; }
    }
    __syncthreads();
    float mean = shs[0] * (1.f / CD);
    float var  = shs2[0] * (1.f / CD) - mean * mean;
    float rstd = rsqrtf(var + CLN_EPS);

    for (int c = tid; c < CD; c += 256) {
        float v = p[c];
        out[(size_t)row * CD + c] = (v - mean) * rstd * gamma[c] + beta[c];
    }
}

// ---------------- launch ----------------
extern "C" void kernel_launch(void* const* d_in, const int* in_sizes, int n_in,
                              void* d_out, int out_size)
{
    const float* x      = (const float*)d_in[0];
    const float* W_in   = (const float*)d_in[1];
    const float* conv_w = (const float*)d_in[2];
    const float* conv_b = (const float*)d_in[3];
    const float* W_x    = (const float*)d_in[4];
    const float* W_dt   = (const float*)d_in[5];
    const float* b_dt   = (const float*)d_in[6];
    const float* A_log  = (const float*)d_in[7];
    const float* D_skip = (const float*)d_in[8];
    const float* W_out  = (const float*)d_in[9];
    const float* ln_g   = (const float*)d_in[10];
    const float* ln_b   = (const float*)d_in[11];
    float* out = (float*)d_out;

    cudaFuncSetAttribute(tgemm5<0>, cudaFuncAttributeMaxDynamicSharedMemorySize, GEMM_SMEM);
    cudaFuncSetAttribute(tgemm5<1>, cudaFuncAttributeMaxDynamicSharedMemorySize, GEMM_SMEM);

    float *p_xz, *p_xcT, *p_xdblT, *p_delta, *p_pre, *p_part, *p_part4;
    uint32_t *p_xp, *p_Winh, *p_Winl, *p_Wxh, *p_Wxl, *p_Wdth, *p_Wdtl, *p_Wouth, *p_Woutl;
    uint16_t *p_xcp, *p_xdp, *p_ygp;
    cudaGetSymbolAddress((void**)&p_xz,    g_xz);
    cudaGetSymbolAddress((void**)&p_xcT,   g_xcT);
    cudaGetSymbolAddress((void**)&p_xdblT, g_xdblT);
    cudaGetSymbolAddress((void**)&p_delta, g_delta);
    cudaGetSymbolAddress((void**)&p_pre,   g_pre);
    cudaGetSymbolAddress((void**)&p_part,  g_part);
    cudaGetSymbolAddress((void**)&p_part4, g_part4);
    cudaGetSymbolAddress((void**)&p_xp,    g_xp);
    cudaGetSymbolAddress((void**)&p_Winh,  g_Winp_h);
    cudaGetSymbolAddress((void**)&p_Winl,  g_Winp_l);
    cudaGetSymbolAddress((void**)&p_Wxh,   g_Wxp_h);
    cudaGetSymbolAddress((void**)&p_Wxl,   g_Wxp_l);
    cudaGetSymbolAddress((void**)&p_Wdth,  g_Wdtp_h);
    cudaGetSymbolAddress((void**)&p_Wdtl,  g_Wdtp_l);
    cudaGetSymbolAddress((void**)&p_Wouth, g_Woutp_h);
    cudaGetSymbolAddress((void**)&p_Woutl, g_Woutp_l);
    cudaGetSymbolAddress((void**)&p_xcp,   g_xcp);
    cudaGetSymbolAddress((void**)&p_xdp,   g_xdp);
    cudaGetSymbolAddress((void**)&p_ygp,   g_ygp);

    pack_x_kernel<<<(CML*(CD/2) + 255)/256, 256>>>(x);
    pack_w_kernel<<<dim3(CD/64, (2*CDIN)/32), 256>>>(W_in, CD, 2*CDIN, p_Winh, p_Winl);
    pack_w3_kernel<<<dim3(CDIN/64, 3 + CDIN/32 + CD/32), 256>>>(
        W_x, W_dt, W_out, p_Wxh, p_Wxl, p_Wdth, p_Wdtl, p_Wouth, p_Woutl);

    dim3 thr(256);

    // G1 (launch #4 -> profiled)
    tgemm5<0><<<dim3((2*CDIN)/128, CML/128), thr, GEMM_SMEM>>>(
        CML, 2*CDIN, p_xp, CD/2, p_Winh, p_Winl, CD/2,
        p_xz, 2*CDIN, nullptr, 0, (CD/2)/16, 0);

    conv_silu_kernel<<<dim3(CML/64, CDIN/32), 256>>>(p_xz, conv_w, conv_b, p_xcp, p_xcT);

    tgemm5<0><<<dim3(1, CML/128, KSPL), thr, GEMM_SMEM>>>(
        CML, CXD, (const uint32_t*)p_xcp, CDIN/2, p_Wxh, p_Wxl, CDIN/2,
        p_part, CXD, nullptr, 0, (CDIN/2/KSPL)/16, CDIN/2/KSPL);

    reduce_xdbl_kernel<<<(CML*CXD + 255)/256, 256>>>(p_part, p_xdblT, p_xdp);

    tgemm5<1><<<dim3(CDIN/128, CML/128), thr, GEMM_SMEM>>>(
        CML, CDIN, (const uint32_t*)p_xdp, CXD/2, p_Wdth, p_Wdtl, CR/2,
        p_delta, CDIN, b_dt, 0, (CR/2)/16, 0);

    scan_kernel<<<(CB*CDIN/2)*32/128, 128>>>(p_delta, p_xcT, p_xdblT, p_xz,
                                             A_log, D_skip, p_ygp);

    // G4 split-K x2: 256 CTAs
    tgemm5<0><<<dim3(CD/128, CML/128, 2), thr, GEMM_SMEM>>>(
        CML, CD, (const uint32_t*)p_ygp, CDIN/2, p_Wouth, p_Woutl, CDIN/2,
        p_part4, CD, nullptr, 0, (CDIN/2/2)/16, CDIN/2/2);

    reduce_pre_kernel<<<(CML*CD + 255)/256, 256>>>(p_part4, p_pre);

    ln_kernel<<<CML, 256>>>(p_pre, ln_g, ln_b, out);
}